// round 5
// baseline (speedup 1.0000x reference)
#include <cuda_runtime.h>

// Problem constants
#define BB      2
#define TT      2048
#define NH      12
#define DH      64
#define CC      768      // d_model
#define C3      2304     // 3*d_model
#define MM      (BB*TT)  // 4096 rows

// Scratch (device globals — no runtime allocation allowed)
__device__ float g_qkv[(size_t)MM * C3];     // [4096, 2304]  (tf32-rounded)
__device__ float g_att[(size_t)MM * CC];     // [4096, 768]   (tf32-rounded)
__device__ float g_xr[(size_t)MM * CC];      // x rounded
__device__ float g_wqkvr[(size_t)C3 * CC];   // Wqkv^T rounded  [2304][768]
__device__ float g_woutr[(size_t)CC * CC];   // Wout^T rounded  [768][768]

// ---------------------------------------------------------------------------
// helpers
// ---------------------------------------------------------------------------
__device__ __forceinline__ unsigned f2tf(float f) {
    unsigned u; asm("cvt.rna.tf32.f32 %0, %1;" : "=r"(u) : "f"(f)); return u;
}
__device__ __forceinline__ float ex2f(float x) {
    float r; asm("ex2.approx.f32 %0, %1;" : "=f"(r) : "f"(x)); return r;
}
__device__ __forceinline__ void mma_tf32(float c[4], const unsigned a[4], const unsigned b[2]) {
    asm volatile(
        "mma.sync.aligned.m16n8k8.row.col.f32.tf32.tf32.f32 "
        "{%0,%1,%2,%3},{%4,%5,%6,%7},{%8,%9},{%0,%1,%2,%3};"
        : "+f"(c[0]), "+f"(c[1]), "+f"(c[2]), "+f"(c[3])
        : "r"(a[0]), "r"(a[1]), "r"(a[2]), "r"(a[3]), "r"(b[0]), "r"(b[1]));
}
__device__ __forceinline__ void cp16(void* dst_smem, const void* src) {
    unsigned d = (unsigned)__cvta_generic_to_shared(dst_smem);
    asm volatile("cp.async.cg.shared.global [%0], [%1], 16;" :: "r"(d), "l"(src));
}
__device__ __forceinline__ void cp_commit() {
    asm volatile("cp.async.commit_group;");
}
template<int N> __device__ __forceinline__ void cp_wait() {
    asm volatile("cp.async.wait_group %0;" :: "n"(N));
}
__device__ __forceinline__ unsigned saddr(const void* p) {
    return (unsigned)__cvta_generic_to_shared(p);
}
// ldmatrix x4 over 32-bit elements: loads a 16-row x 4-word tile; per-lane
// row address = base + (lane&15)*rowStrideBytes + ((lane>>4)*16) already
// folded into the caller-provided address.
__device__ __forceinline__ void ldsm4(unsigned r[4], unsigned addr) {
    asm volatile("ldmatrix.sync.aligned.m8n8.x4.shared.b16 {%0,%1,%2,%3}, [%4];"
                 : "=r"(r[0]), "=r"(r[1]), "=r"(r[2]), "=r"(r[3]) : "r"(addr));
}

// ---------------------------------------------------------------------------
// Pre-pass kernels
// ---------------------------------------------------------------------------
__global__ void round_tf32_kernel(const float* __restrict__ in, float* __restrict__ out, int n4)
{
    int i = blockIdx.x * blockDim.x + threadIdx.x;
    if (i < n4) {
        float4 v = ((const float4*)in)[i];
        uint4 u = make_uint4(f2tf(v.x), f2tf(v.y), f2tf(v.z), f2tf(v.w));
        ((float4*)out)[i] = *(float4*)&u;
    }
}

// in: [K][N] row-major; out: [N][K] row-major, tf32-rounded.
__global__ void transpose_round_kernel(const float* __restrict__ in, float* __restrict__ out,
                                       int K, int N)
{
    __shared__ float t[32][33];
    int n0 = blockIdx.x * 32, k0 = blockIdx.y * 32;
    int tx = threadIdx.x, ty = threadIdx.y;     // 32 x 8
#pragma unroll
    for (int j = 0; j < 4; j++)
        t[ty + j * 8][tx] = in[(size_t)(k0 + ty + j * 8) * N + n0 + tx];
    __syncthreads();
#pragma unroll
    for (int j = 0; j < 4; j++)
        out[(size_t)(n0 + ty + j * 8) * K + k0 + tx] =
            __uint_as_float(f2tf(t[tx][ty + j * 8]));
}

// ---------------------------------------------------------------------------
// TF32 tensor-core GEMM with bias; B pre-transposed ([N][K]).
// cp.async 2-stage; fragments fed by ldmatrix.
// C[M,N] = A[M,K] @ B[K,N] + bias[N].
// 128x128 block tile, BK=32, 256 threads (8 warps), warp tile 64x32.
// smem per stage: A[128][36] + Bt[128][36] = 36864 B; 2 stages = 73728 B.
// ---------------------------------------------------------------------------
#define GA_W   (128*36)
#define GSTAGE (2*GA_W)
#define GEMM_SMEM (2 * GSTAGE * 4)

template<bool ROUND_OUT>
__global__ __launch_bounds__(256, 2)
void gemm_tf32_lm(const float* __restrict__ A, const float* __restrict__ Bt,
                  const float* __restrict__ bias, float* __restrict__ C,
                  int M, int N, int K)
{
    extern __shared__ unsigned smg[];

    const int tid  = threadIdx.x;
    const int lane = tid & 31;
    const int w    = tid >> 5;
    const int wm   = (w >> 2) * 64;
    const int wn   = (w & 3) * 32;
    const int g    = lane >> 2;
    const int tig  = lane & 3;
    const int lr   = lane & 15;          // ldmatrix row within 16
    const int lc   = (lane >> 4) * 4;    // ldmatrix col offset (words)
    const int rowBase = blockIdx.y * 128;
    const int colBase = blockIdx.x * 128;

    float acc[4][4][4];
#pragma unroll
    for (int mt = 0; mt < 4; mt++)
#pragma unroll
        for (int nt = 0; nt < 4; nt++)
#pragma unroll
            for (int j = 0; j < 4; j++) acc[mt][nt][j] = 0.f;

    auto loadTile = [&](int k0, int s) {
        unsigned* As = smg + s * GSTAGE;
        unsigned* Bs = As + GA_W;
#pragma unroll
        for (int i = 0; i < 4; i++) {
            int c = tid + i * 256;
            int r = c >> 3, c4 = c & 7;
            cp16(&As[r * 36 + c4 * 4], A  + (size_t)(rowBase + r) * K + k0 + c4 * 4);
        }
#pragma unroll
        for (int i = 0; i < 4; i++) {
            int c = tid + i * 256;
            int r = c >> 3, c4 = c & 7;
            cp16(&Bs[r * 36 + c4 * 4], Bt + (size_t)(colBase + r) * K + k0 + c4 * 4);
        }
    };

    loadTile(0, 0);
    cp_commit();

    int buf = 0;
    for (int k0 = 0; k0 < K; k0 += 32) {
        if (k0 + 32 < K) { loadTile(k0 + 32, buf ^ 1); cp_commit(); cp_wait<1>(); }
        else             { cp_wait<0>(); }
        __syncthreads();

        unsigned aB = saddr(smg + buf * GSTAGE)        + (unsigned)(((wm + lr) * 36 + lc) * 4);
        unsigned bB = saddr(smg + buf * GSTAGE + GA_W) + (unsigned)(((wn + lr) * 36 + lc) * 4);

#pragma unroll
        for (int ks = 0; ks < 4; ks++) {
            unsigned af[4][4];
#pragma unroll
            for (int mt = 0; mt < 4; mt++)
                ldsm4(af[mt], aB + mt * (16 * 36 * 4) + ks * 32);
            unsigned b0[4], b1[4];
            ldsm4(b0, bB + ks * 32);
            ldsm4(b1, bB + 16 * 36 * 4 + ks * 32);
            unsigned bf[4][2] = {{b0[0], b0[2]}, {b0[1], b0[3]},
                                 {b1[0], b1[2]}, {b1[1], b1[3]}};
#pragma unroll
            for (int mt = 0; mt < 4; mt++)
#pragma unroll
                for (int nt = 0; nt < 4; nt++)
                    mma_tf32(acc[mt][nt], af[mt], bf[nt]);
        }
        __syncthreads();
        buf ^= 1;
    }

#pragma unroll
    for (int mt = 0; mt < 4; mt++) {
        int r0 = rowBase + wm + mt * 16 + g;
#pragma unroll
        for (int nt = 0; nt < 4; nt++) {
            int c = colBase + wn + nt * 8 + 2 * tig;
            float2 b2 = *(const float2*)(bias + c);
            float v00 = acc[mt][nt][0] + b2.x, v01 = acc[mt][nt][1] + b2.y;
            float v10 = acc[mt][nt][2] + b2.x, v11 = acc[mt][nt][3] + b2.y;
            float2 o0, o1;
            if (ROUND_OUT) {
                o0.x = __uint_as_float(f2tf(v00)); o0.y = __uint_as_float(f2tf(v01));
                o1.x = __uint_as_float(f2tf(v10)); o1.y = __uint_as_float(f2tf(v11));
            } else {
                o0.x = v00; o0.y = v01; o1.x = v10; o1.y = v11;
            }
            *(float2*)(C + (size_t)r0 * N + c)       = o0;
            *(float2*)(C + (size_t)(r0 + 8) * N + c) = o1;
        }
    }
}

// ---------------------------------------------------------------------------
// Causal flash attention, TF32 tensor cores, cp.async double-buffered K/V,
// ldmatrix fragment feeds for Q, K, P.  (R3 shape: 64 q / 128 thr per block.)
// Dyn smem: QP[64][68] | 2 x (Ks[64][68] + Vs[64][72]) = 89088 B.
// ---------------------------------------------------------------------------
#define QP_W    (64*68)
#define KS_W    (64*68)
#define VS_W    (64*72)
#define FSTAGE  (KS_W + VS_W)
#define FLASH_SMEM ((QP_W + 2*FSTAGE) * 4)

__global__ __launch_bounds__(128)
void flash_tf32(const float* __restrict__ qkv, float* __restrict__ out)
{
    extern __shared__ unsigned sm[];
    unsigned (*QP)[68] = (unsigned(*)[68])sm;

    const int b    = blockIdx.z;
    const int h    = blockIdx.y;
    const int qb   = gridDim.x - 1 - blockIdx.x;   // heavy blocks first
    const int tid  = threadIdx.x;
    const int lane = tid & 31;
    const int w    = tid >> 5;
    const int g    = lane >> 2;
    const int tig  = lane & 3;
    const int lr   = lane & 15;
    const int lc   = (lane >> 4) * 4;
    const int m0   = w * 16;

    const float SC = 0.125f * 1.44269504088896341f;  // scale * log2(e)

    auto loadKV = [&](int kb, int s) {
        unsigned* Ks = sm + QP_W + s * FSTAGE;
        unsigned* Vs = Ks + KS_W;
        const float* kp = qkv + (size_t)(b * TT + kb * 64) * C3 + CC + h * DH;
#pragma unroll
        for (int i = 0; i < 8; i++) {
            int idx = tid + i * 128;
            int r = idx >> 4, c4 = idx & 15;
            const float* rp = kp + (size_t)r * C3 + c4 * 4;
            cp16(&Ks[r * 68 + c4 * 4], rp);
            cp16(&Vs[r * 72 + c4 * 4], rp + CC);
        }
    };

    loadKV(0, 0);
    cp_commit();

    // ---- load Q tile (pre-rounded) ----
    {
        const float* qp = qkv + (size_t)(b * TT + qb * 64) * C3 + h * DH;
#pragma unroll
        for (int i = 0; i < 8; i++) {
            int idx = tid + i * 128;
            int r = idx >> 4, c4 = idx & 15;
            *(float4*)&QP[r][c4 * 4] = *(const float4*)(qp + (size_t)r * C3 + c4 * 4);
        }
    }
    __syncthreads();

    // per-warp QP base address for ldmatrix (rows m0..m0+15)
    const unsigned qpB = saddr(sm) + (unsigned)(((m0 + lr) * 68 + lc) * 4);

    // ---- persistent Q fragments (ldmatrix) ----
    unsigned qf[8][4];
#pragma unroll
    for (int kt = 0; kt < 8; kt++) ldsm4(qf[kt], qpB + kt * 32);

    float o[8][4];
#pragma unroll
    for (int nt = 0; nt < 8; nt++)
#pragma unroll
        for (int j = 0; j < 4; j++) o[nt][j] = 0.f;

    float mr0 = -1e30f, mr1 = -1e30f, l0 = 0.f, l1 = 0.f;
    const int qg0 = qb * 64 + m0 + g;
    const int qg1 = qg0 + 8;

    int buf = 0;
    for (int kb = 0; kb <= qb; kb++) {
        if (kb < qb) { loadKV(kb + 1, buf ^ 1); cp_commit(); cp_wait<1>(); }
        else         { cp_wait<0>(); }
        __syncthreads();

        unsigned (*Vs)[72] = (unsigned(*)[72])(sm + QP_W + buf * FSTAGE + KS_W);
        const unsigned ksB = saddr(sm + QP_W + buf * FSTAGE)
                           + (unsigned)((lr * 68 + lc) * 4);

        // ---- S = Q K^T (ldmatrix-fed) ----
        float s[8][4];
#pragma unroll
        for (int nt = 0; nt < 8; nt++)
            s[nt][0] = s[nt][1] = s[nt][2] = s[nt][3] = 0.f;
#pragma unroll
        for (int kt = 0; kt < 8; kt++) {
#pragma unroll
            for (int i = 0; i < 4; i++) {
                unsigned r[4];
                ldsm4(r, ksB + i * (16 * 68 * 4) + kt * 32);
                unsigned be[2] = {r[0], r[2]};
                unsigned bo[2] = {r[1], r[3]};
                mma_tf32(s[2 * i],     qf[kt], be);
                mma_tf32(s[2 * i + 1], qf[kt], bo);
            }
        }
#pragma unroll
        for (int nt = 0; nt < 8; nt++) {
            s[nt][0] *= SC; s[nt][1] *= SC; s[nt][2] *= SC; s[nt][3] *= SC;
        }

        // ---- causal mask (diagonal block only) ----
        if (kb == qb) {
#pragma unroll
            for (int nt = 0; nt < 8; nt++) {
                int kg = kb * 64 + nt * 8 + 2 * tig;
                if (kg > qg0)     s[nt][0] = -1e30f;
                if (kg + 1 > qg0) s[nt][1] = -1e30f;
                if (kg > qg1)     s[nt][2] = -1e30f;
                if (kg + 1 > qg1) s[nt][3] = -1e30f;
            }
        }

        // ---- online softmax (base-2) ----
        float vm0 = -1e30f, vm1 = -1e30f;
#pragma unroll
        for (int nt = 0; nt < 8; nt++) {
            vm0 = fmaxf(vm0, fmaxf(s[nt][0], s[nt][1]));
            vm1 = fmaxf(vm1, fmaxf(s[nt][2], s[nt][3]));
        }
        vm0 = fmaxf(vm0, __shfl_xor_sync(0xffffffffu, vm0, 1));
        vm0 = fmaxf(vm0, __shfl_xor_sync(0xffffffffu, vm0, 2));
        vm1 = fmaxf(vm1, __shfl_xor_sync(0xffffffffu, vm1, 1));
        vm1 = fmaxf(vm1, __shfl_xor_sync(0xffffffffu, vm1, 2));

        float mn0 = fmaxf(mr0, vm0), mn1 = fmaxf(mr1, vm1);
        float corr0 = ex2f(mr0 - mn0), corr1 = ex2f(mr1 - mn1);
        mr0 = mn0; mr1 = mn1;

        float sum0 = 0.f, sum1 = 0.f;
#pragma unroll
        for (int nt = 0; nt < 8; nt++) {
            s[nt][0] = ex2f(s[nt][0] - mn0);
            s[nt][1] = ex2f(s[nt][1] - mn0);
            s[nt][2] = ex2f(s[nt][2] - mn1);
            s[nt][3] = ex2f(s[nt][3] - mn1);
            sum0 += s[nt][0] + s[nt][1];
            sum1 += s[nt][2] + s[nt][3];
        }
        sum0 += __shfl_xor_sync(0xffffffffu, sum0, 1);
        sum0 += __shfl_xor_sync(0xffffffffu, sum0, 2);
        sum1 += __shfl_xor_sync(0xffffffffu, sum1, 1);
        sum1 += __shfl_xor_sync(0xffffffffu, sum1, 2);
        l0 = l0 * corr0 + sum0;
        l1 = l1 * corr1 + sum1;

#pragma unroll
        for (int nt = 0; nt < 8; nt++) {
            o[nt][0] *= corr0; o[nt][1] *= corr0;
            o[nt][2] *= corr1; o[nt][3] *= corr1;
        }

        // ---- stage P into QP (warp-local rows) ----
        __syncwarp();
#pragma unroll
        for (int nt = 0; nt < 8; nt++) {
            uint2 u0 = make_uint2(f2tf(s[nt][0]), f2tf(s[nt][1]));
            uint2 u1 = make_uint2(f2tf(s[nt][2]), f2tf(s[nt][3]));
            *(uint2*)&QP[m0 + g][nt * 8 + 2 * tig]     = u0;
            *(uint2*)&QP[m0 + 8 + g][nt * 8 + 2 * tig] = u1;
        }
        __syncwarp();

        // ---- O += P V (P via ldmatrix, V scalar) ----
#pragma unroll
        for (int kt = 0; kt < 8; kt++) {
            unsigned pa[4];
            ldsm4(pa, qpB + kt * 32);
#pragma unroll
            for (int nt = 0; nt < 8; nt++) {
                unsigned bb[2];
                bb[0] = Vs[kt * 8 + tig][nt * 8 + g];
                bb[1] = Vs[kt * 8 + tig + 4][nt * 8 + g];
                mma_tf32(o[nt], pa, bb);
            }
        }
        __syncthreads();   // all warps done with K/V `buf` before refill
        buf ^= 1;
    }

    // ---- normalize and write out (tf32-rounded for the next GEMM) ----
    const float inv0 = 1.f / l0, inv1 = 1.f / l1;
    float* op0 = out + (size_t)(b * TT + qb * 64 + m0 + g) * CC + h * DH;
    float* op1 = op0 + (size_t)8 * CC;
#pragma unroll
    for (int nt = 0; nt < 8; nt++) {
        float2 r0, r1;
        r0.x = __uint_as_float(f2tf(o[nt][0] * inv0));
        r0.y = __uint_as_float(f2tf(o[nt][1] * inv0));
        r1.x = __uint_as_float(f2tf(o[nt][2] * inv1));
        r1.y = __uint_as_float(f2tf(o[nt][3] * inv1));
        *(float2*)(op0 + nt * 8 + 2 * tig) = r0;
        *(float2*)(op1 + nt * 8 + 2 * tig) = r1;
    }
}

// ---------------------------------------------------------------------------
// kernel_launch
// ---------------------------------------------------------------------------
extern "C" void kernel_launch(void* const* d_in, const int* in_sizes, int n_in,
                              void* d_out, int out_size)
{
    const float* x    = (const float*)d_in[0];
    // d_in[1] = mask (static causal; unused)
    const float* Wqkv = (const float*)d_in[2];
    const float* bqkv = (const float*)d_in[3];
    const float* Wout = (const float*)d_in[4];
    const float* bout = (const float*)d_in[5];
    float* out = (float*)d_out;

    float* qkv;   cudaGetSymbolAddress((void**)&qkv,   g_qkv);
    float* att;   cudaGetSymbolAddress((void**)&att,   g_att);
    float* xr;    cudaGetSymbolAddress((void**)&xr,    g_xr);
    float* wqkvr; cudaGetSymbolAddress((void**)&wqkvr, g_wqkvr);
    float* woutr; cudaGetSymbolAddress((void**)&woutr, g_woutr);

    static bool configured = false;
    if (!configured) {
        cudaFuncSetAttribute(gemm_tf32_lm<true>,
                             cudaFuncAttributeMaxDynamicSharedMemorySize, GEMM_SMEM);
        cudaFuncSetAttribute(gemm_tf32_lm<false>,
                             cudaFuncAttributeMaxDynamicSharedMemorySize, GEMM_SMEM);
        cudaFuncSetAttribute(flash_tf32,
                             cudaFuncAttributeMaxDynamicSharedMemorySize, FLASH_SMEM);
        configured = true;
    }

    // 0) pre-pass: round x; transpose+round weights
    round_tf32_kernel<<<(MM * CC / 4 + 255) / 256, 256>>>(x, xr, MM * CC / 4);
    {
        dim3 blk(32, 8);
        dim3 g1(C3 / 32, CC / 32);
        transpose_round_kernel<<<g1, blk>>>(Wqkv, wqkvr, CC, C3);
        dim3 g2(CC / 32, CC / 32);
        transpose_round_kernel<<<g2, blk>>>(Wout, woutr, CC, CC);
    }

    // 1) QKV projection: [4096,768] @ [768,2304] + bias  (rounded output)
    {
        dim3 grid(C3 / 128, MM / 128);
        gemm_tf32_lm<true><<<grid, 256, GEMM_SMEM>>>(xr, wqkvr, bqkv, qkv, MM, C3, CC);
    }
    // 2) Causal multi-head attention (rounded output)
    {
        dim3 grid(TT / 64, NH, BB);
        flash_tf32<<<grid, 128, FLASH_SMEM>>>(qkv, att);
    }
    // 3) Output projection: [4096,768] @ [768,768] + bias (exact fp32 output)
    {
        dim3 grid(CC / 128, MM / 128);
        gemm_tf32_lm<false><<<grid, 256, GEMM_SMEM>>>(att, woutr, bout, out, MM, CC, CC);
    }
}

// round 7
// speedup vs baseline: 1.9905x; 1.9905x over previous
#include <cuda_runtime.h>
#include <cuda_fp16.h>
#include <cstdint>

// Problem constants
#define BB      2
#define TT      2048
#define NH      12
#define DH      64
#define CC      768      // d_model
#define C3      2304     // 3*d_model
#define MM      (BB*TT)  // 4096 rows

// Scratch (device globals — no runtime allocation allowed)
__device__ __half g_qkvh[(size_t)MM * C3];    // [4096, 2304] fp16
__device__ __half g_atth[(size_t)MM * CC];    // [4096, 768]  fp16
__device__ __half g_xh[(size_t)MM * CC];      // x fp16
__device__ __half g_wqkvh[(size_t)C3 * CC];   // Wqkv^T fp16 [2304][768]
__device__ __half g_wouth[(size_t)CC * CC];   // Wout^T fp16 [768][768]

// ---------------------------------------------------------------------------
// helpers
// ---------------------------------------------------------------------------
__device__ __forceinline__ float ex2f(float x) {
    float r; asm("ex2.approx.f32 %0, %1;" : "=f"(r) : "f"(x)); return r;
}
__device__ __forceinline__ unsigned packh2(float lo, float hi) {
    __half2 h = __floats2half2_rn(lo, hi);
    return *reinterpret_cast<unsigned*>(&h);
}
__device__ __forceinline__ void mma_f16(float c[4], const unsigned a[4], const unsigned b[2]) {
    asm volatile(
        "mma.sync.aligned.m16n8k16.row.col.f32.f16.f16.f32 "
        "{%0,%1,%2,%3},{%4,%5,%6,%7},{%8,%9},{%0,%1,%2,%3};"
        : "+f"(c[0]), "+f"(c[1]), "+f"(c[2]), "+f"(c[3])
        : "r"(a[0]), "r"(a[1]), "r"(a[2]), "r"(a[3]), "r"(b[0]), "r"(b[1]));
}
__device__ __forceinline__ void cp16s(unsigned dst_saddr, const void* src) {
    asm volatile("cp.async.cg.shared.global [%0], [%1], 16;" :: "r"(dst_saddr), "l"(src));
}
__device__ __forceinline__ void cp_commit() {
    asm volatile("cp.async.commit_group;");
}
template<int N> __device__ __forceinline__ void cp_wait() {
    asm volatile("cp.async.wait_group %0;" :: "n"(N));
}
__device__ __forceinline__ unsigned saddr(const void* p) {
    return (unsigned)__cvta_generic_to_shared(p);
}
// ldmatrix x4 transposed (b16): four 8x8 transposed tiles
__device__ __forceinline__ void ldsm4t(unsigned r[4], unsigned addr) {
    asm volatile("ldmatrix.sync.aligned.m8n8.x4.trans.shared.b16 {%0,%1,%2,%3}, [%4];"
                 : "=r"(r[0]), "=r"(r[1]), "=r"(r[2]), "=r"(r[3]) : "r"(addr));
}

// ---------------------------------------------------------------------------
// Pre-pass kernels
// ---------------------------------------------------------------------------
__global__ void f32_to_f16_kernel(const float* __restrict__ in, __half* __restrict__ out, int n4)
{
    int i = blockIdx.x * blockDim.x + threadIdx.x;
    if (i < n4) {
        float4 v = ((const float4*)in)[i];
        __half2 h0 = __floats2half2_rn(v.x, v.y);
        __half2 h1 = __floats2half2_rn(v.z, v.w);
        ((__half2*)out)[2 * i]     = h0;
        ((__half2*)out)[2 * i + 1] = h1;
    }
}

// in: [K][N] f32 row-major; out: [N][K] fp16 row-major.
__global__ void transpose_f16_kernel(const float* __restrict__ in, __half* __restrict__ out,
                                     int K, int N)
{
    __shared__ float t[32][33];
    int n0 = blockIdx.x * 32, k0 = blockIdx.y * 32;
    int tx = threadIdx.x, ty = threadIdx.y;     // 32 x 8
#pragma unroll
    for (int j = 0; j < 4; j++)
        t[ty + j * 8][tx] = in[(size_t)(k0 + ty + j * 8) * N + n0 + tx];
    __syncthreads();
#pragma unroll
    for (int j = 0; j < 4; j++)
        out[(size_t)(n0 + ty + j * 8) * K + k0 + tx] = __float2half_rn(t[tx][ty + j * 8]);
}

// ---------------------------------------------------------------------------
// FP16 tensor-core GEMM with bias: C[M,N] = A[M,K] @ Bt[N,K]^T + bias[N]
// A, Bt fp16 (Bt = B transposed, K contiguous). 128x128 block tile, BK=64
// halves, 2-stage cp.async, 256 threads (8 warps), warp tile 64x32, k16 MMA.
// Columns c < CC are multiplied by qmul (softmax-scale folding for Q).
// smem: 2 stages x (A[128][72] + B[128][72]) halves = 73728 B.
// ---------------------------------------------------------------------------
#define GSTAGE_B 36864
#define GEMM_SMEM (2 * GSTAGE_B)

template<bool HALF_OUT>
__global__ __launch_bounds__(256, 2)
void gemm_f16(const __half* __restrict__ A, const __half* __restrict__ Bt,
              const float* __restrict__ bias, void* __restrict__ Cv,
              int M, int N, int K, float qmul)
{
    extern __shared__ char smg[];
    const unsigned base = saddr(smg);

    const int tid  = threadIdx.x;
    const int lane = tid & 31;
    const int w    = tid >> 5;
    const int wm   = (w >> 2) * 64;
    const int wn   = (w & 3) * 32;
    const int g    = lane >> 2;
    const int tig  = lane & 3;
    const int rowBase = blockIdx.y * 128;
    const int colBase = blockIdx.x * 128;

    float acc[4][4][4];
#pragma unroll
    for (int mt = 0; mt < 4; mt++)
#pragma unroll
        for (int nt = 0; nt < 4; nt++)
#pragma unroll
            for (int j = 0; j < 4; j++) acc[mt][nt][j] = 0.f;

    // 128 rows x 128B (64 halves), row stride 144B; 1024 chunks per tile, 4/thread
    auto loadTile = [&](int k0, int s) {
        unsigned ab = base + (unsigned)s * GSTAGE_B;
        unsigned bb = ab + 18432u;
#pragma unroll
        for (int i = 0; i < 4; i++) {
            int idx = tid + i * 256;
            int r = idx >> 3, c = idx & 7;
            cp16s(ab + r * 144 + c * 16, A  + (size_t)(rowBase + r) * K + k0 + c * 8);
        }
#pragma unroll
        for (int i = 0; i < 4; i++) {
            int idx = tid + i * 256;
            int r = idx >> 3, c = idx & 7;
            cp16s(bb + r * 144 + c * 16, Bt + (size_t)(colBase + r) * K + k0 + c * 8);
        }
    };

    loadTile(0, 0);
    cp_commit();

    int buf = 0;
    for (int k0 = 0; k0 < K; k0 += 64) {
        if (k0 + 64 < K) { loadTile(k0 + 64, buf ^ 1); cp_commit(); cp_wait<1>(); }
        else             { cp_wait<0>(); }
        __syncthreads();

        const unsigned* As = (const unsigned*)(smg + buf * GSTAGE_B);
        const unsigned* Bs = As + 18432 / 4;

#pragma unroll
        for (int ks = 0; ks < 4; ks++) {
            unsigned af[4][4], bf[4][2];
#pragma unroll
            for (int mt = 0; mt < 4; mt++) {
                int m = wm + mt * 16 + g;
                af[mt][0] = As[m * 36 + tig + 8 * ks];
                af[mt][1] = As[(m + 8) * 36 + tig + 8 * ks];
                af[mt][2] = As[m * 36 + tig + 4 + 8 * ks];
                af[mt][3] = As[(m + 8) * 36 + tig + 4 + 8 * ks];
            }
#pragma unroll
            for (int nt = 0; nt < 4; nt++) {
                int n = wn + nt * 8 + g;
                bf[nt][0] = Bs[n * 36 + tig + 8 * ks];
                bf[nt][1] = Bs[n * 36 + tig + 4 + 8 * ks];
            }
#pragma unroll
            for (int mt = 0; mt < 4; mt++)
#pragma unroll
                for (int nt = 0; nt < 4; nt++)
                    mma_f16(acc[mt][nt], af[mt], bf[nt]);
        }
        __syncthreads();
        buf ^= 1;
    }

#pragma unroll
    for (int mt = 0; mt < 4; mt++) {
        int r0 = rowBase + wm + mt * 16 + g;
#pragma unroll
        for (int nt = 0; nt < 4; nt++) {
            int c = colBase + wn + nt * 8 + 2 * tig;
            float2 b2 = *(const float2*)(bias + c);
            float sc = (c < CC) ? qmul : 1.f;
            float v00 = (acc[mt][nt][0] + b2.x) * sc, v01 = (acc[mt][nt][1] + b2.y) * sc;
            float v10 = (acc[mt][nt][2] + b2.x) * sc, v11 = (acc[mt][nt][3] + b2.y) * sc;
            if (HALF_OUT) {
                __half* C = (__half*)Cv;
                *(unsigned*)(C + (size_t)r0 * N + c)       = packh2(v00, v01);
                *(unsigned*)(C + (size_t)(r0 + 8) * N + c) = packh2(v10, v11);
            } else {
                float* C = (float*)Cv;
                *(float2*)(C + (size_t)r0 * N + c)       = make_float2(v00, v01);
                *(float2*)(C + (size_t)(r0 + 8) * N + c) = make_float2(v10, v11);
            }
        }
    }
}

// ---------------------------------------------------------------------------
// Causal flash attention, FP16 tensor cores (m16n8k16), cp.async double-
// buffered K/V, ldmatrix.trans V fragments, register-direct P fragments.
// 64 queries / 128 threads per block; Q pre-scaled by softmax*log2(e).
// smem (halves, row stride 72): Q[64][72] | 2 x (K[64][72] + V[64][72])
//   = 9216 + 2*18432 = 46080 B  -> 4 blocks/SM.
// ---------------------------------------------------------------------------
#define FQ_B     9216
#define FKV_B    18432
#define FLASH_SMEM (FQ_B + 2 * FKV_B)

__global__ __launch_bounds__(128, 4)
void flash_f16(const __half* __restrict__ qkv, __half* __restrict__ out)
{
    extern __shared__ char smf[];
    const unsigned base = saddr(smf);

    const int b    = blockIdx.z;
    const int h    = blockIdx.y;
    const int qb   = gridDim.x - 1 - blockIdx.x;   // heavy blocks first
    const int tid  = threadIdx.x;
    const int lane = tid & 31;
    const int w    = tid >> 5;
    const int g    = lane >> 2;
    const int tig  = lane & 3;
    const int m0   = w * 16;

    auto loadKV = [&](int kb, int s) {
        unsigned kbase = base + FQ_B + (unsigned)s * FKV_B;
        unsigned vbase = kbase + 9216u;
        const __half* kp = qkv + (size_t)(b * TT + kb * 64) * C3 + CC + h * DH;
#pragma unroll
        for (int i = 0; i < 4; i++) {
            int idx = tid + i * 128;           // 0..511
            int r = idx >> 3, c = idx & 7;
            const __half* rp = kp + (size_t)r * C3 + c * 8;
            cp16s(kbase + r * 144 + c * 16, rp);
            cp16s(vbase + r * 144 + c * 16, rp + CC);
        }
    };

    loadKV(0, 0);
    cp_commit();

    // ---- load Q tile (pre-scaled fp16) ----
    {
        const __half* qp = qkv + (size_t)(b * TT + qb * 64) * C3 + h * DH;
#pragma unroll
        for (int i = 0; i < 4; i++) {
            int idx = tid + i * 128;
            int r = idx >> 3, c = idx & 7;
            *(uint4*)(smf + r * 144 + c * 16) = *(const uint4*)(qp + (size_t)r * C3 + c * 8);
        }
    }
    __syncthreads();

    // ---- persistent Q fragments (4 k16-steps) ----
    unsigned qf[4][4];
    {
        const unsigned* Qs = (const unsigned*)smf;
#pragma unroll
        for (int kt = 0; kt < 4; kt++) {
            qf[kt][0] = Qs[(m0 + g) * 36 + tig + 8 * kt];
            qf[kt][1] = Qs[(m0 + 8 + g) * 36 + tig + 8 * kt];
            qf[kt][2] = Qs[(m0 + g) * 36 + tig + 4 + 8 * kt];
            qf[kt][3] = Qs[(m0 + 8 + g) * 36 + tig + 4 + 8 * kt];
        }
    }

    float o[8][4];
#pragma unroll
    for (int nt = 0; nt < 8; nt++)
#pragma unroll
        for (int j = 0; j < 4; j++) o[nt][j] = 0.f;

    float mr0 = -1e30f, mr1 = -1e30f, l0 = 0.f, l1 = 0.f;
    const int qg0 = qb * 64 + m0 + g;
    const int qg1 = qg0 + 8;

    // per-lane ldmatrix base offset within a V tile
    const unsigned vlane = (unsigned)((lane & 15) * 144 + (lane >> 4) * 16);

    int buf = 0;
    for (int kb = 0; kb <= qb; kb++) {
        if (kb < qb) { loadKV(kb + 1, buf ^ 1); cp_commit(); cp_wait<1>(); }
        else         { cp_wait<0>(); }
        __syncthreads();

        const unsigned kstage = base + FQ_B + (unsigned)buf * FKV_B;
        const unsigned* Ks = (const unsigned*)(smf + FQ_B + buf * FKV_B);
        const unsigned vstage = kstage + 9216u;

        // ---- S = Q K^T ----
        float s[8][4];
#pragma unroll
        for (int nt = 0; nt < 8; nt++) {
            s[nt][0] = s[nt][1] = s[nt][2] = s[nt][3] = 0.f;
            int n = nt * 8 + g;
#pragma unroll
            for (int kt = 0; kt < 4; kt++) {
                unsigned bb[2];
                bb[0] = Ks[n * 36 + tig + 8 * kt];
                bb[1] = Ks[n * 36 + tig + 4 + 8 * kt];
                mma_f16(s[nt], qf[kt], bb);
            }
        }

        // ---- causal mask (diagonal block only) ----
        if (kb == qb) {
#pragma unroll
            for (int nt = 0; nt < 8; nt++) {
                int kg = kb * 64 + nt * 8 + 2 * tig;
                if (kg > qg0)     s[nt][0] = -1e30f;
                if (kg + 1 > qg0) s[nt][1] = -1e30f;
                if (kg > qg1)     s[nt][2] = -1e30f;
                if (kg + 1 > qg1) s[nt][3] = -1e30f;
            }
        }

        // ---- online softmax (base-2; scale folded into Q) ----
        float vm0 = -1e30f, vm1 = -1e30f;
#pragma unroll
        for (int nt = 0; nt < 8; nt++) {
            vm0 = fmaxf(vm0, fmaxf(s[nt][0], s[nt][1]));
            vm1 = fmaxf(vm1, fmaxf(s[nt][2], s[nt][3]));
        }
        vm0 = fmaxf(vm0, __shfl_xor_sync(0xffffffffu, vm0, 1));
        vm0 = fmaxf(vm0, __shfl_xor_sync(0xffffffffu, vm0, 2));
        vm1 = fmaxf(vm1, __shfl_xor_sync(0xffffffffu, vm1, 1));
        vm1 = fmaxf(vm1, __shfl_xor_sync(0xffffffffu, vm1, 2));

        float mn0 = fmaxf(mr0, vm0), mn1 = fmaxf(mr1, vm1);
        float corr0 = ex2f(mr0 - mn0), corr1 = ex2f(mr1 - mn1);
        mr0 = mn0; mr1 = mn1;

        float sum0 = 0.f, sum1 = 0.f;
#pragma unroll
        for (int nt = 0; nt < 8; nt++) {
            s[nt][0] = ex2f(s[nt][0] - mn0);
            s[nt][1] = ex2f(s[nt][1] - mn0);
            s[nt][2] = ex2f(s[nt][2] - mn1);
            s[nt][3] = ex2f(s[nt][3] - mn1);
            sum0 += s[nt][0] + s[nt][1];
            sum1 += s[nt][2] + s[nt][3];
        }
        sum0 += __shfl_xor_sync(0xffffffffu, sum0, 1);
        sum0 += __shfl_xor_sync(0xffffffffu, sum0, 2);
        sum1 += __shfl_xor_sync(0xffffffffu, sum1, 1);
        sum1 += __shfl_xor_sync(0xffffffffu, sum1, 2);
        l0 = l0 * corr0 + sum0;
        l1 = l1 * corr1 + sum1;

#pragma unroll
        for (int nt = 0; nt < 8; nt++) {
            o[nt][0] *= corr0; o[nt][1] *= corr0;
            o[nt][2] *= corr1; o[nt][3] *= corr1;
        }

        // ---- O += P V : P fragments direct from registers, V via ldmatrix.trans
#pragma unroll
        for (int kt = 0; kt < 4; kt++) {
            unsigned pa[4];
            pa[0] = packh2(s[2 * kt][0],     s[2 * kt][1]);
            pa[1] = packh2(s[2 * kt][2],     s[2 * kt][3]);
            pa[2] = packh2(s[2 * kt + 1][0], s[2 * kt + 1][1]);
            pa[3] = packh2(s[2 * kt + 1][2], s[2 * kt + 1][3]);
            unsigned vrowbase = vstage + vlane + (unsigned)(kt * 16 * 144);
#pragma unroll
            for (int ntp = 0; ntp < 4; ntp++) {
                unsigned vr[4];
                ldsm4t(vr, vrowbase + ntp * 32);
                unsigned b0[2] = {vr[0], vr[1]};
                unsigned b1[2] = {vr[2], vr[3]};
                mma_f16(o[2 * ntp],     pa, b0);
                mma_f16(o[2 * ntp + 1], pa, b1);
            }
        }
        __syncthreads();
        buf ^= 1;
    }

    // ---- normalize and write out (fp16 for the next GEMM) ----
    const float inv0 = 1.f / l0, inv1 = 1.f / l1;
    __half* op0 = out + (size_t)(b * TT + qb * 64 + m0 + g) * CC + h * DH;
    __half* op1 = op0 + (size_t)8 * CC;
#pragma unroll
    for (int nt = 0; nt < 8; nt++) {
        *(unsigned*)(op0 + nt * 8 + 2 * tig) = packh2(o[nt][0] * inv0, o[nt][1] * inv0);
        *(unsigned*)(op1 + nt * 8 + 2 * tig) = packh2(o[nt][2] * inv1, o[nt][3] * inv1);
    }
}

// ---------------------------------------------------------------------------
// kernel_launch
// ---------------------------------------------------------------------------
extern "C" void kernel_launch(void* const* d_in, const int* in_sizes, int n_in,
                              void* d_out, int out_size)
{
    const float* x    = (const float*)d_in[0];
    // d_in[1] = mask (static causal; unused)
    const float* Wqkv = (const float*)d_in[2];
    const float* bqkv = (const float*)d_in[3];
    const float* Wout = (const float*)d_in[4];
    const float* bout = (const float*)d_in[5];
    float* out = (float*)d_out;

    __half* qkvh;  cudaGetSymbolAddress((void**)&qkvh,  g_qkvh);
    __half* atth;  cudaGetSymbolAddress((void**)&atth,  g_atth);
    __half* xh;    cudaGetSymbolAddress((void**)&xh,    g_xh);
    __half* wqkvh; cudaGetSymbolAddress((void**)&wqkvh, g_wqkvh);
    __half* wouth; cudaGetSymbolAddress((void**)&wouth, g_wouth);

    static bool configured = false;
    if (!configured) {
        cudaFuncSetAttribute(gemm_f16<true>,
                             cudaFuncAttributeMaxDynamicSharedMemorySize, GEMM_SMEM);
        cudaFuncSetAttribute(gemm_f16<false>,
                             cudaFuncAttributeMaxDynamicSharedMemorySize, GEMM_SMEM);
        cudaFuncSetAttribute(flash_f16,
                             cudaFuncAttributeMaxDynamicSharedMemorySize, FLASH_SMEM);
        configured = true;
    }

    const float QSCALE = 0.125f * 1.44269504088896341f;   // 1/sqrt(64) * log2(e)

    // 0) pre-pass: convert x to fp16; transpose+convert weights
    f32_to_f16_kernel<<<(MM * CC / 4 + 255) / 256, 256>>>(x, xh, MM * CC / 4);
    {
        dim3 blk(32, 8);
        dim3 g1(C3 / 32, CC / 32);
        transpose_f16_kernel<<<g1, blk>>>(Wqkv, wqkvh, CC, C3);
        dim3 g2(CC / 32, CC / 32);
        transpose_f16_kernel<<<g2, blk>>>(Wout, wouth, CC, CC);
    }

    // 1) QKV projection (q-columns pre-scaled by QSCALE; fp16 output)
    {
        dim3 grid(C3 / 128, MM / 128);
        gemm_f16<true><<<grid, 256, GEMM_SMEM>>>(xh, wqkvh, bqkv, qkvh,
                                                 MM, C3, CC, QSCALE);
    }
    // 2) Causal multi-head attention (fp16 output)
    {
        dim3 grid(TT / 64, NH, BB);
        flash_f16<<<grid, 128, FLASH_SMEM>>>(qkvh, atth);
    }
    // 3) Output projection (fp32 output)
    {
        dim3 grid(CC / 128, MM / 128);
        gemm_f16<false><<<grid, 256, GEMM_SMEM>>>(atth, wouth, bout, out,
                                                  MM, CC, CC, 1.0f);
    }
}